// round 5
// baseline (speedup 1.0000x reference)
#include <cuda_runtime.h>
#include <math.h>
#include <stdint.h>

// ---------------- problem dims ----------------
constexpr int B_   = 16;
constexpr int NQ   = 32;
constexpr int NN   = 128;
constexpr int T_   = 352;
constexpr int D_   = 768;
constexpr int H_   = 8;
constexpr int NLAY = 6;
constexpr int FF   = 3072;
constexpr int L_   = NQ + NN + T_;   // 512
constexpr int TS   = NQ + NN;        // 160
constexpr int HD   = D_ / H_;        // 96
constexpr float NEGB = -1e9f;
constexpr int QKVS = 3 * D_;         // 2304

// ---------------- device scratch ----------------
__device__ float g_x  [B_ * L_ * D_];
__device__ float g_tmp[B_ * L_ * D_];
__device__ float g_ctx[B_ * L_ * D_];      // holds tf32-bit floats (attention out)
__device__ float g_qkv[B_ * L_ * 3 * D_];
__device__ float g_ff [B_ * L_ * FF];      // holds tf32-bit floats (gelu out)

// tf32 pre-converted operand copies
__device__ uint32_t g_xtf    [B_ * L_ * D_];
__device__ uint32_t g_qkvw_tf[NLAY * D_ * 3 * D_];
__device__ uint32_t g_aow_tf [NLAY * D_ * D_];
__device__ uint32_t g_ff1w_tf[NLAY * D_ * FF];
__device__ uint32_t g_ff2w_tf[NLAY * FF * D_];
__device__ uint32_t g_gpw_tf [D_ * D_];
__device__ uint32_t g_gnf_tf [B_ * NN * D_];

// ---------------- tf32 helpers ----------------
__device__ __forceinline__ uint32_t f2tf(float x) {
    uint32_t r;
    asm("cvt.rna.tf32.f32 %0, %1;" : "=r"(r) : "f"(x));
    return r;
}

__device__ __forceinline__ void mma_tf32(float c[4], const uint32_t a[4],
                                         const uint32_t b[2]) {
    asm volatile(
        "mma.sync.aligned.m16n8k8.row.col.f32.tf32.tf32.f32 "
        "{%0,%1,%2,%3}, {%4,%5,%6,%7}, {%8,%9}, {%0,%1,%2,%3};"
        : "+f"(c[0]), "+f"(c[1]), "+f"(c[2]), "+f"(c[3])
        : "r"(a[0]), "r"(a[1]), "r"(a[2]), "r"(a[3]), "r"(b[0]), "r"(b[1]));
}

__device__ __forceinline__ void cp_async16(uint32_t smem, const void* gptr) {
    asm volatile("cp.async.ca.shared.global [%0], [%1], 16;"
                 :: "r"(smem), "l"(gptr));
}
#define CP_COMMIT() asm volatile("cp.async.commit_group;")
#define CP_WAIT1()  asm volatile("cp.async.wait_group 1;")

// ============================================================================
// TF32 GEMM: operands already tf32 in gmem. cp.async 3-stage pipeline,
// one __syncthreads per K-tile. 128x128 block, 8 warps of 64x32, K-tile 16.
// EPI: 0 = +bias (fp32 out)  1 = +bias+resid (fp32 out)  2 = gelu (tf32 out)
// ============================================================================
constexpr int ASTR = 20;
constexpr int BSTR = 136;
constexpr int TG_SMEM = (3 * 128 * ASTR + 3 * 16 * BSTR) * 4;   // 56832 B

template <int EPI>
__global__ __launch_bounds__(256)
void tgemm(const float* __restrict__ A, const float* __restrict__ Bm,
           const float* __restrict__ bias, const float* __restrict__ resid,
           float* __restrict__ C, int M, int N, int K, int mapGraph)
{
    extern __shared__ uint32_t dsm[];
    uint32_t* As = dsm;                       // 3 stages of [128][ASTR]
    uint32_t* Bs = dsm + 3 * 128 * ASTR;      // 3 stages of [16][BSTR]

    const int tid  = threadIdx.x;
    const int br   = blockIdx.y, bc = blockIdx.x;
    const int lane = tid & 31,  wid = tid >> 5;
    const int wm = (wid >> 2) * 64;
    const int wn = (wid & 3) * 32;
    const int lq = lane >> 2;
    const int lr = lane & 3;

    const uint32_t sAb = (uint32_t)__cvta_generic_to_shared(As);
    const uint32_t sBb = (uint32_t)__cvta_generic_to_shared(Bs);

    float acc[4][4][4];
#pragma unroll
    for (int mt = 0; mt < 4; mt++)
#pragma unroll
        for (int nt = 0; nt < 4; nt++)
#pragma unroll
            for (int r = 0; r < 4; r++) acc[mt][nt][r] = 0.f;

    const int nkt = K >> 4;

    // precomputed per-thread load coordinates
    const int ar0 = tid >> 2,        ac0 = (tid & 3) << 2;        // + same for tid+256
    const int brw = tid >> 5,        bcw = (tid & 31) << 2;

    auto issue = [&](int kt, int st) {
        // A: 2 chunks of 16B per thread
        cp_async16(sAb + (uint32_t)((st * 128 + ar0) * ASTR + ac0) * 4,
                   A + (size_t)(br * 128 + ar0) * K + kt * 16 + ac0);
        cp_async16(sAb + (uint32_t)((st * 128 + ar0 + 64) * ASTR + ac0) * 4,
                   A + (size_t)(br * 128 + ar0 + 64) * K + kt * 16 + ac0);
        // B: 2 chunks of 16B per thread
        cp_async16(sBb + (uint32_t)((st * 16 + brw) * BSTR + bcw) * 4,
                   Bm + (size_t)(kt * 16 + brw) * N + bc * 128 + bcw);
        cp_async16(sBb + (uint32_t)((st * 16 + brw + 8) * BSTR + bcw) * 4,
                   Bm + (size_t)(kt * 16 + brw + 8) * N + bc * 128 + bcw);
    };

    auto compute = [&](int st) {
        const uint32_t* Ab = As + st * 128 * ASTR;
        const uint32_t* Bb = Bs + st * 16 * BSTR;
#pragma unroll
        for (int k8 = 0; k8 < 16; k8 += 8) {
            uint32_t af[4][4], bf[4][2];
#pragma unroll
            for (int mt = 0; mt < 4; mt++) {
                const uint32_t* p = &Ab[(wm + mt * 16 + lq) * ASTR + k8 + lr];
                af[mt][0] = p[0];
                af[mt][1] = p[8 * ASTR];
                af[mt][2] = p[4];
                af[mt][3] = p[8 * ASTR + 4];
            }
#pragma unroll
            for (int nt = 0; nt < 4; nt++) {
                const uint32_t* p = &Bb[(k8 + lr) * BSTR + wn + nt * 8 + lq];
                bf[nt][0] = p[0];
                bf[nt][1] = p[4 * BSTR];
            }
#pragma unroll
            for (int mt = 0; mt < 4; mt++)
#pragma unroll
                for (int nt = 0; nt < 4; nt++)
                    mma_tf32(acc[mt][nt], af[mt], bf[nt]);
        }
    };

    issue(0, 0); CP_COMMIT();
    issue(1, 1); CP_COMMIT();

    for (int kt = 0; kt < nkt; kt++) {
        CP_WAIT1();
        __syncthreads();
        if (kt + 2 < nkt) issue(kt + 2, (kt + 2) % 3);
        CP_COMMIT();
        compute(kt % 3);
    }

    // ---- epilogue ----
#pragma unroll
    for (int mt = 0; mt < 4; mt++) {
        int rbase = br * 128 + wm + mt * 16 + lq;
#pragma unroll
        for (int nt = 0; nt < 4; nt++) {
            int col = bc * 128 + wn + nt * 8 + lr * 2;
            float b0 = bias[col], b1 = bias[col + 1];
#pragma unroll
            for (int hh = 0; hh < 2; hh++) {
                int row = rbase + hh * 8;
                int orow = mapGraph ? (row / NN) * L_ + NQ + (row % NN) : row;
                float v0 = acc[mt][nt][hh * 2 + 0] + b0;
                float v1 = acc[mt][nt][hh * 2 + 1] + b1;
                if (EPI == 1) {
                    v0 += resid[(size_t)row * N + col];
                    v1 += resid[(size_t)row * N + col + 1];
                }
                if (EPI == 2) {
                    v0 = 0.5f * v0 * (1.0f + erff(v0 * 0.7071067811865475f));
                    v1 = 0.5f * v1 * (1.0f + erff(v1 * 0.7071067811865475f));
                    v0 = __uint_as_float(f2tf(v0));   // consumed as tf32 GEMM-A
                    v1 = __uint_as_float(f2tf(v1));
                }
                float2 o = make_float2(v0, v1);
                *(float2*)(C + (size_t)orow * N + col) = o;
            }
        }
    }
}

// ============================================================================
// tf32 conversion pass (weights / inputs); n must be a multiple of 4
// ============================================================================
__global__ void cvt_tf(const float* __restrict__ in, uint32_t* __restrict__ out,
                       int n)
{
    int i = (blockIdx.x * blockDim.x + threadIdx.x) * 4;
    if (i >= n) return;
    float4 v = *(const float4*)(in + i);
    uint4 o = make_uint4(f2tf(v.x), f2tf(v.y), f2tf(v.z), f2tf(v.w));
    *(uint4*)(out + i) = o;
}

// ============================================================================
// Row LayerNorm (D=768), warp-shuffle reductions; dual fp32 + tf32 output
// ============================================================================
__global__ __launch_bounds__(256)
void ln_kernel(const float* __restrict__ in, float* __restrict__ out,
               uint32_t* __restrict__ out_tf,
               const float* __restrict__ g, const float* __restrict__ bta,
               const float* __restrict__ pos, const float* __restrict__ tok)
{
    const int row = blockIdx.x;
    const int l = row % L_;
    const int tid = threadIdx.x;
    const int lane = tid & 31, wid = tid >> 5;
    const float* ip = in + (size_t)row * D_;

    float v[3];
    float s = 0.f;
#pragma unroll
    for (int i = 0; i < 3; i++) {
        int d = tid + i * 256;
        float x = ip[d];
        if (pos) x += pos[l * D_ + d] + tok[d];
        v[i] = x;
        s += x;
    }
#pragma unroll
    for (int o = 16; o > 0; o >>= 1) s += __shfl_xor_sync(0xffffffffu, s, o);

    __shared__ float red[8];
    __shared__ float smean, sinv;
    if (lane == 0) red[wid] = s;
    __syncthreads();
    if (tid == 0) {
        float t = 0.f;
#pragma unroll
        for (int j = 0; j < 8; j++) t += red[j];
        smean = t * (1.0f / 768.0f);
    }
    __syncthreads();
    float mean = smean;

    float ss = 0.f;
#pragma unroll
    for (int i = 0; i < 3; i++) {
        float d0 = v[i] - mean;
        ss += d0 * d0;
    }
#pragma unroll
    for (int o = 16; o > 0; o >>= 1) ss += __shfl_xor_sync(0xffffffffu, ss, o);
    if (lane == 0) red[wid] = ss;
    __syncthreads();
    if (tid == 0) {
        float t = 0.f;
#pragma unroll
        for (int j = 0; j < 8; j++) t += red[j];
        sinv = rsqrtf(t * (1.0f / 768.0f) + 1e-12f);
    }
    __syncthreads();
    float inv = sinv;

    float* op = out + (size_t)row * D_;
    uint32_t* ot = out_tf + (size_t)row * D_;
#pragma unroll
    for (int i = 0; i < 3; i++) {
        int d = tid + i * 256;
        float y = (v[i] - mean) * inv * g[d] + bta[d];
        op[d] = y;
        ot[d] = f2tf(y);
    }
}

// ============================================================================
// TF32 tensor-core attention (round-4 structure; ctx stored as tf32 bits)
// ============================================================================
constexpr int KVW = 104;
constexpr int SW2 = 520;
constexpr int ATTN_SMEM = (64 * KVW * 2 + 64 * SW2) * 4 + L_ * 4;

__global__ __launch_bounds__(256)
void attn_mma(const float* __restrict__ qkv, float* __restrict__ ctx,
              const int* __restrict__ text_atts, const int* __restrict__ graph_mask)
{
    const int bh = blockIdx.x;
    const int b = bh / H_, h = bh % H_;
    const int qt = blockIdx.y;
    const int tid = threadIdx.x;
    const int lane = tid & 31, wid = tid >> 5;
    const int lq = lane >> 2, lr = lane & 3;

    extern __shared__ uint32_t smu[];
    uint32_t* Qs = smu;
    uint32_t* KV = Qs + 64 * KVW;
    uint32_t* Sb = KV + 64 * KVW;
    int* keep = (int*)(Sb + 64 * SW2);

    for (int j = tid; j < L_; j += 256)
        keep[j] = (j < NQ) ? 1
                : (j < TS) ? graph_mask[b * NN + (j - NQ)]
                           : text_atts[b * T_ + (j - TS)];

    const float* qbase = qkv + (size_t)(b * L_ + qt * 64) * QKVS + h * HD;
#pragma unroll
    for (int i = 0; i < 6; i++) {
        int e = tid + i * 256;
        int r = e / 24, c4 = (e % 24) * 4;
        float4 v = *(const float4*)(qbase + (size_t)r * QKVS + c4);
        uint32_t* p = &Qs[r * KVW + c4];
        p[0] = f2tf(v.x); p[1] = f2tf(v.y); p[2] = f2tf(v.z); p[3] = f2tf(v.w);
    }

    const int wm  = (wid >> 1) * 16;
    const int wnS = (wid & 1) * 32;
    const int wnV = (wid & 1) * 48;
    const float scale = 0.10206207261596577f;

    float4 pre[6];
    auto ldKV = [&](int kc, int which) {
        const float* base = qkv + (size_t)(b * L_ + kc * 64) * QKVS + which * D_ + h * HD;
#pragma unroll
        for (int i = 0; i < 6; i++) {
            int e = tid + i * 256;
            int r = e / 24, c4 = (e % 24) * 4;
            pre[i] = *(const float4*)(base + (size_t)r * QKVS + c4);
        }
    };
    auto stKV = [&]() {
#pragma unroll
        for (int i = 0; i < 6; i++) {
            int e = tid + i * 256;
            int r = e / 24, c4 = (e % 24) * 4;
            uint32_t* p = &KV[r * KVW + c4];
            p[0] = f2tf(pre[i].x); p[1] = f2tf(pre[i].y);
            p[2] = f2tf(pre[i].z); p[3] = f2tf(pre[i].w);
        }
    };

    // ---------------- score phase ----------------
    ldKV(0, 1);
    stKV();
    __syncthreads();
    for (int kc = 0; kc < 8; kc++) {
        if (kc < 7) ldKV(kc + 1, 1);

        float sacc[4][4];
#pragma unroll
        for (int nt = 0; nt < 4; nt++)
#pragma unroll
            for (int r = 0; r < 4; r++) sacc[nt][r] = 0.f;

#pragma unroll
        for (int k8 = 0; k8 < 96; k8 += 8) {
            uint32_t af[4];
            const uint32_t* qp = &Qs[(wm + lq) * KVW + k8 + lr];
            af[0] = qp[0];
            af[1] = qp[8 * KVW];
            af[2] = qp[4];
            af[3] = qp[8 * KVW + 4];
#pragma unroll
            for (int nt = 0; nt < 4; nt++) {
                const uint32_t* kp = &KV[(wnS + nt * 8 + lq) * KVW + k8 + lr];
                uint32_t bf[2] = {kp[0], kp[4]};
                mma_tf32(sacc[nt], af, bf);
            }
        }

        float* Sf = (float*)Sb;
#pragma unroll
        for (int nt = 0; nt < 4; nt++) {
            int kg = kc * 64 + wnS + nt * 8 + 2 * lr;
            bool k0 = keep[kg] != 0, k1 = keep[kg + 1] != 0;
#pragma unroll
            for (int half = 0; half < 2; half++) {
                int qrow = wm + lq + half * 8;
                int qg = qt * 64 + qrow;
                bool qok = keep[qg] != 0;
                bool ok0 = qok && k0, ok1 = qok && k1;
                if (qg < TS) {
                    if (kg     >= TS) ok0 = false;
                    if (kg + 1 >= TS) ok1 = false;
                } else {
                    if (kg     >= TS && qg < kg)     ok0 = false;
                    if (kg + 1 >= TS && qg < kg + 1) ok1 = false;
                }
                float v0 = sacc[nt][half * 2 + 0] * scale + (ok0 ? 0.f : NEGB);
                float v1 = sacc[nt][half * 2 + 1] * scale + (ok1 ? 0.f : NEGB);
                *(float2*)&Sf[qrow * SW2 + kg] = make_float2(v0, v1);
            }
        }
        __syncthreads();
        if (kc < 7) { stKV(); __syncthreads(); }
    }

    // ---------------- softmax: 4 threads per row ----------------
    ldKV(0, 2);
    {
        int r = tid >> 2, p = tid & 3;
        float* row = (float*)Sb + r * SW2 + p * 128;
        float m = -INFINITY;
#pragma unroll 4
        for (int k = 0; k < 128; k++) m = fmaxf(m, row[k]);
        m = fmaxf(m, __shfl_xor_sync(0xffffffffu, m, 1));
        m = fmaxf(m, __shfl_xor_sync(0xffffffffu, m, 2));
        float sum = 0.f;
#pragma unroll 4
        for (int k = 0; k < 128; k++) {
            float e = __expf(row[k] - m);
            row[k] = e;
            sum += e;
        }
        sum += __shfl_xor_sync(0xffffffffu, sum, 1);
        sum += __shfl_xor_sync(0xffffffffu, sum, 2);
        float inv = 1.f / sum;
        uint32_t* rowb = Sb + r * SW2 + p * 128;
#pragma unroll 4
        for (int k = 0; k < 128; k++) rowb[k] = f2tf(row[k] * inv);
    }
    stKV();
    __syncthreads();

    // ---------------- P @ V ----------------
    float oacc[6][4];
#pragma unroll
    for (int nt = 0; nt < 6; nt++)
#pragma unroll
        for (int r = 0; r < 4; r++) oacc[nt][r] = 0.f;

    for (int kc = 0; kc < 8; kc++) {
        if (kc < 7) ldKV(kc + 1, 2);

#pragma unroll
        for (int k8 = 0; k8 < 64; k8 += 8) {
            uint32_t af[4];
            const uint32_t* pp = &Sb[(wm + lq) * SW2 + kc * 64 + k8 + lr];
            af[0] = pp[0];
            af[1] = pp[8 * SW2];
            af[2] = pp[4];
            af[3] = pp[8 * SW2 + 4];
#pragma unroll
            for (int nt = 0; nt < 6; nt++) {
                const uint32_t* vp = &KV[(k8 + lr) * KVW + wnV + nt * 8 + lq];
                uint32_t bf[2] = {vp[0], vp[4 * KVW]};
                mma_tf32(oacc[nt], af, bf);
            }
        }
        __syncthreads();
        if (kc < 7) { stKV(); __syncthreads(); }
    }

#pragma unroll
    for (int nt = 0; nt < 6; nt++) {
#pragma unroll
        for (int half = 0; half < 2; half++) {
            int qrow = qt * 64 + wm + lq + half * 8;
            int col = h * HD + wnV + nt * 8 + 2 * lr;
            // store as tf32 bits: consumed directly as GEMM-A by attn-out GEMM
            float2 o = make_float2(__uint_as_float(f2tf(oacc[nt][half * 2 + 0])),
                                   __uint_as_float(f2tf(oacc[nt][half * 2 + 1])));
            *(float2*)(ctx + (size_t)(b * L_ + qrow) * D_ + col) = o;
        }
    }
}

// ============================================================================
// misc elementwise
// ============================================================================
__global__ void fill_embed(const float* __restrict__ qtok,
                           const float* __restrict__ temb,
                           float* __restrict__ out)
{
    int idx = blockIdx.x * blockDim.x + threadIdx.x;
    if (idx >= B_ * L_ * D_) return;
    int rem = idx % (L_ * D_);
    int b = idx / (L_ * D_);
    int l = rem / D_, d = rem % D_;
    if (l < NQ)
        out[idx] = qtok[l * D_ + d];
    else if (l >= TS)
        out[idx] = temb[(size_t)(b * T_ + (l - TS)) * D_ + d];
}

__global__ void copy_out(const float* __restrict__ x, float* __restrict__ out, int n)
{
    int idx = blockIdx.x * blockDim.x + threadIdx.x;
    if (idx >= n) return;
    int rem = idx % (T_ * D_);
    int b = idx / (T_ * D_);
    int t = rem / D_, d = rem % D_;
    out[idx] = x[(size_t)(b * L_ + TS + t) * D_ + d];
}

// ============================================================================
// launcher
// ============================================================================
extern "C" void kernel_launch(void* const* d_in, const int* in_sizes, int n_in,
                              void* d_out, int out_size)
{
    const float* gnf     = (const float*)d_in[0];
    const float* temb    = (const float*)d_in[1];
    const int*   tatt    = (const int*)  d_in[2];
    const int*   gmask   = (const int*)  d_in[3];
    const float* qtok    = (const float*)d_in[4];
    const float* gproj_w = (const float*)d_in[5];
    const float* gproj_b = (const float*)d_in[6];
    const float* pos     = (const float*)d_in[7];
    const float* tok     = (const float*)d_in[8];
    const float* elng    = (const float*)d_in[9];
    const float* elnb    = (const float*)d_in[10];
    const float* qkvw    = (const float*)d_in[11];
    const float* qkvb    = (const float*)d_in[12];
    const float* aow     = (const float*)d_in[13];
    const float* aob     = (const float*)d_in[14];
    const float* ln1g    = (const float*)d_in[15];
    const float* ln1b    = (const float*)d_in[16];
    const float* ff1w    = (const float*)d_in[17];
    const float* ff1b    = (const float*)d_in[18];
    const float* ff2w    = (const float*)d_in[19];
    const float* ff2b    = (const float*)d_in[20];
    const float* ln2g    = (const float*)d_in[21];
    const float* ln2b    = (const float*)d_in[22];

    float *px, *ptmp, *pctx, *pqkv, *pff;
    uint32_t *pxtf, *pqkvwt, *paowt, *pff1wt, *pff2wt, *pgpwt, *pgnft;
    cudaGetSymbolAddress((void**)&px,    g_x);
    cudaGetSymbolAddress((void**)&ptmp,  g_tmp);
    cudaGetSymbolAddress((void**)&pctx,  g_ctx);
    cudaGetSymbolAddress((void**)&pqkv,  g_qkv);
    cudaGetSymbolAddress((void**)&pff,   g_ff);
    cudaGetSymbolAddress((void**)&pxtf,  g_xtf);
    cudaGetSymbolAddress((void**)&pqkvwt, g_qkvw_tf);
    cudaGetSymbolAddress((void**)&paowt,  g_aow_tf);
    cudaGetSymbolAddress((void**)&pff1wt, g_ff1w_tf);
    cudaGetSymbolAddress((void**)&pff2wt, g_ff2w_tf);
    cudaGetSymbolAddress((void**)&pgpwt,  g_gpw_tf);
    cudaGetSymbolAddress((void**)&pgnft,  g_gnf_tf);

    cudaFuncSetAttribute(attn_mma, cudaFuncAttributeMaxDynamicSharedMemorySize,
                         ATTN_SMEM);
    cudaFuncSetAttribute(tgemm<0>, cudaFuncAttributeMaxDynamicSharedMemorySize,
                         TG_SMEM);
    cudaFuncSetAttribute(tgemm<1>, cudaFuncAttributeMaxDynamicSharedMemorySize,
                         TG_SMEM);
    cudaFuncSetAttribute(tgemm<2>, cudaFuncAttributeMaxDynamicSharedMemorySize,
                         TG_SMEM);

    const int NROWS = B_ * L_;   // 8192

    // ---- pre-convert weights + graph features to tf32 (RNA) ----
    auto cvt = [](const float* in, uint32_t* out, int n) {
        cvt_tf<<<(n / 4 + 255) / 256, 256>>>(in, out, n);
    };
    cvt(qkvw,    pqkvwt, NLAY * D_ * 3 * D_);
    cvt(aow,     paowt,  NLAY * D_ * D_);
    cvt(ff1w,    pff1wt, NLAY * D_ * FF);
    cvt(ff2w,    pff2wt, NLAY * FF * D_);
    cvt(gproj_w, pgpwt,  D_ * D_);
    cvt(gnf,     pgnft,  B_ * NN * D_);

    // ---- embeddings ----
    fill_embed<<<(B_ * L_ * D_ + 255) / 256, 256>>>(qtok, temb, ptmp);
    tgemm<0><<<dim3(D_ / 128, (B_ * NN) / 128), 256, TG_SMEM>>>(
        (const float*)pgnft, (const float*)pgpwt, gproj_b, nullptr, ptmp,
        B_ * NN, D_, D_, 1);
    ln_kernel<<<NROWS, 256>>>(ptmp, px, pxtf, elng, elnb, pos, tok);

    // ---- 6 encoder layers ----
    for (int i = 0; i < NLAY; i++) {
        tgemm<0><<<dim3((3 * D_) / 128, NROWS / 128), 256, TG_SMEM>>>(
            (const float*)pxtf, (const float*)(pqkvwt + (size_t)i * D_ * 3 * D_),
            qkvb + (size_t)i * 3 * D_, nullptr, pqkv, NROWS, 3 * D_, D_, 0);

        attn_mma<<<dim3(B_ * H_, L_ / 64), 256, ATTN_SMEM>>>(pqkv, pctx, tatt, gmask);

        tgemm<1><<<dim3(D_ / 128, NROWS / 128), 256, TG_SMEM>>>(
            pctx, (const float*)(paowt + (size_t)i * D_ * D_),
            aob + (size_t)i * D_, px, ptmp, NROWS, D_, D_, 0);
        ln_kernel<<<NROWS, 256>>>(ptmp, px, pxtf, ln1g + (size_t)i * D_,
                                  ln1b + (size_t)i * D_, nullptr, nullptr);

        tgemm<2><<<dim3(FF / 128, NROWS / 128), 256, TG_SMEM>>>(
            (const float*)pxtf, (const float*)(pff1wt + (size_t)i * D_ * FF),
            ff1b + (size_t)i * FF, nullptr, pff, NROWS, FF, D_, 0);

        tgemm<1><<<dim3(D_ / 128, NROWS / 128), 256, TG_SMEM>>>(
            pff, (const float*)(pff2wt + (size_t)i * FF * D_),
            ff2b + (size_t)i * D_, px, ptmp, NROWS, D_, FF, 0);
        ln_kernel<<<NROWS, 256>>>(ptmp, px, pxtf, ln2g + (size_t)i * D_,
                                  ln2b + (size_t)i * D_, nullptr, nullptr);
    }

    // ---- output: text rows ----
    copy_out<<<(out_size + 255) / 256, 256>>>(px, (float*)d_out, out_size);
}

// round 7
// speedup vs baseline: 1.3648x; 1.3648x over previous
#include <cuda_runtime.h>
#include <math.h>
#include <stdint.h>

// ---------------- problem dims ----------------
constexpr int B_   = 16;
constexpr int NQ   = 32;
constexpr int NN   = 128;
constexpr int T_   = 352;
constexpr int D_   = 768;
constexpr int H_   = 8;
constexpr int NLAY = 6;
constexpr int FF   = 3072;
constexpr int L_   = NQ + NN + T_;   // 512
constexpr int TS   = NQ + NN;        // 160
constexpr int HD   = D_ / H_;        // 96
constexpr float NEGB = -1e9f;
constexpr int QKVS = 3 * D_;         // 2304

// ---------------- device scratch ----------------
__device__ float g_x  [B_ * L_ * D_];
__device__ float g_tmp[B_ * L_ * D_];
__device__ float g_ctx[B_ * L_ * D_];      // tf32-bit floats (attention out)
__device__ float g_qkv[B_ * L_ * 3 * D_];
__device__ float g_ff [B_ * L_ * FF];      // tf32-bit floats (gelu out)

// tf32 pre-converted operand copies
__device__ uint32_t g_xtf    [B_ * L_ * D_];
__device__ uint32_t g_qkvw_tf[NLAY * D_ * 3 * D_];
__device__ uint32_t g_aow_tf [NLAY * D_ * D_];
__device__ uint32_t g_ff1w_tf[NLAY * D_ * FF];
__device__ uint32_t g_ff2w_tf[NLAY * FF * D_];
__device__ uint32_t g_gpw_tf [D_ * D_];
__device__ uint32_t g_gnf_tf [B_ * NN * D_];

// ---------------- tf32 helpers ----------------
__device__ __forceinline__ uint32_t f2tf(float x) {
    uint32_t r;
    asm("cvt.rna.tf32.f32 %0, %1;" : "=r"(r) : "f"(x));
    return r;
}

__device__ __forceinline__ void mma_tf32(float c[4], const uint32_t a[4],
                                         const uint32_t b[2]) {
    asm volatile(
        "mma.sync.aligned.m16n8k8.row.col.f32.tf32.tf32.f32 "
        "{%0,%1,%2,%3}, {%4,%5,%6,%7}, {%8,%9}, {%0,%1,%2,%3};"
        : "+f"(c[0]), "+f"(c[1]), "+f"(c[2]), "+f"(c[3])
        : "r"(a[0]), "r"(a[1]), "r"(a[2]), "r"(a[3]), "r"(b[0]), "r"(b[1]));
}

// ============================================================================
// TF32 GEMM — R4's measured-good register-staged double-buffered mainloop,
// but operands are pre-converted tf32 in gmem: stAB has NO conversions.
// EPI: 0 = +bias (fp32 out)  1 = +bias+resid (fp32 out)  2 = gelu (tf32 out)
// ============================================================================
constexpr int ASTR = 20;
constexpr int BSTR = 136;

template <int EPI>
__global__ __launch_bounds__(256)
void tgemm(const uint32_t* __restrict__ A, const uint32_t* __restrict__ Bm,
           const float* __restrict__ bias, const float* __restrict__ resid,
           float* __restrict__ C, int M, int N, int K, int mapGraph)
{
    __shared__ uint32_t As[2][128 * ASTR];
    __shared__ uint32_t Bs[2][16 * BSTR];

    const int tid  = threadIdx.x;
    const int br   = blockIdx.y, bc = blockIdx.x;
    const int lane = tid & 31,  wid = tid >> 5;
    const int wm = (wid >> 2) * 64;
    const int wn = (wid & 3) * 32;
    const int lq = lane >> 2;
    const int lr = lane & 3;

    float acc[4][4][4];
#pragma unroll
    for (int mt = 0; mt < 4; mt++)
#pragma unroll
        for (int nt = 0; nt < 4; nt++)
#pragma unroll
            for (int r = 0; r < 4; r++) acc[mt][nt][r] = 0.f;

    const int nkt = K >> 4;
    uint4 pa[2], pb[2];

    auto ldA = [&](int kt) {
#pragma unroll
        for (int i = 0; i < 2; i++) {
            int id  = tid + i * 256;
            int row = id >> 2, cg = (id & 3) << 2;
            pa[i] = *(const uint4*)(A + (size_t)(br * 128 + row) * K + kt * 16 + cg);
        }
    };
    auto ldB = [&](int kt) {
#pragma unroll
        for (int i = 0; i < 2; i++) {
            int id  = tid + i * 256;
            int row = id >> 5, cg = (id & 31) << 2;
            pb[i] = *(const uint4*)(Bm + (size_t)(kt * 16 + row) * N + bc * 128 + cg);
        }
    };
    auto stAB = [&](int buf) {
#pragma unroll
        for (int i = 0; i < 2; i++) {
            int id  = tid + i * 256;
            int row = id >> 2, cg = (id & 3) << 2;
            *(uint4*)&As[buf][row * ASTR + cg] = pa[i];
        }
#pragma unroll
        for (int i = 0; i < 2; i++) {
            int id  = tid + i * 256;
            int row = id >> 5, cg = (id & 31) << 2;
            *(uint4*)&Bs[buf][row * BSTR + cg] = pb[i];
        }
    };
    auto compute = [&](int buf) {
#pragma unroll
        for (int k8 = 0; k8 < 16; k8 += 8) {
            uint32_t af[4][4], bf[4][2];
#pragma unroll
            for (int mt = 0; mt < 4; mt++) {
                const uint32_t* p = &As[buf][(wm + mt * 16 + lq) * ASTR + k8 + lr];
                af[mt][0] = p[0];
                af[mt][1] = p[8 * ASTR];
                af[mt][2] = p[4];
                af[mt][3] = p[8 * ASTR + 4];
            }
#pragma unroll
            for (int nt = 0; nt < 4; nt++) {
                const uint32_t* p = &Bs[buf][(k8 + lr) * BSTR + wn + nt * 8 + lq];
                bf[nt][0] = p[0];
                bf[nt][1] = p[4 * BSTR];
            }
#pragma unroll
            for (int mt = 0; mt < 4; mt++)
#pragma unroll
                for (int nt = 0; nt < 4; nt++)
                    mma_tf32(acc[mt][nt], af[mt], bf[nt]);
        }
    };

    ldA(0); ldB(0);
    stAB(0);
    __syncthreads();
    for (int kt = 0; kt < nkt; kt++) {
        int buf = kt & 1;
        bool more = (kt + 1 < nkt);
        if (more) { ldA(kt + 1); ldB(kt + 1); }
        compute(buf);
        if (more) stAB(buf ^ 1);
        __syncthreads();
    }

    // ---- epilogue ----
#pragma unroll
    for (int mt = 0; mt < 4; mt++) {
        int rbase = br * 128 + wm + mt * 16 + lq;
#pragma unroll
        for (int nt = 0; nt < 4; nt++) {
            int col = bc * 128 + wn + nt * 8 + lr * 2;
            float b0 = bias[col], b1 = bias[col + 1];
#pragma unroll
            for (int hh = 0; hh < 2; hh++) {
                int row = rbase + hh * 8;
                int orow = mapGraph ? (row / NN) * L_ + NQ + (row % NN) : row;
                float v0 = acc[mt][nt][hh * 2 + 0] + b0;
                float v1 = acc[mt][nt][hh * 2 + 1] + b1;
                if (EPI == 1) {
                    v0 += resid[(size_t)row * N + col];
                    v1 += resid[(size_t)row * N + col + 1];
                }
                if (EPI == 2) {
                    v0 = 0.5f * v0 * (1.0f + erff(v0 * 0.7071067811865475f));
                    v1 = 0.5f * v1 * (1.0f + erff(v1 * 0.7071067811865475f));
                    v0 = __uint_as_float(f2tf(v0));   // consumed as tf32 GEMM-A
                    v1 = __uint_as_float(f2tf(v1));
                }
                float2 o = make_float2(v0, v1);
                *(float2*)(C + (size_t)orow * N + col) = o;
            }
        }
    }
}

// ============================================================================
// tf32 conversion pass (weights / inputs); n multiple of 4
// ============================================================================
__global__ void cvt_tf(const float* __restrict__ in, uint32_t* __restrict__ out,
                       int n)
{
    int i = (blockIdx.x * blockDim.x + threadIdx.x) * 4;
    if (i >= n) return;
    float4 v = *(const float4*)(in + i);
    uint4 o = make_uint4(f2tf(v.x), f2tf(v.y), f2tf(v.z), f2tf(v.w));
    *(uint4*)(out + i) = o;
}

// ============================================================================
// Row LayerNorm (D=768), warp-shuffle reductions; dual fp32 + tf32 output
// ============================================================================
__global__ __launch_bounds__(256)
void ln_kernel(const float* __restrict__ in, float* __restrict__ out,
               uint32_t* __restrict__ out_tf,
               const float* __restrict__ g, const float* __restrict__ bta,
               const float* __restrict__ pos, const float* __restrict__ tok)
{
    const int row = blockIdx.x;
    const int l = row % L_;
    const int tid = threadIdx.x;
    const int lane = tid & 31, wid = tid >> 5;
    const float* ip = in + (size_t)row * D_;

    float v[3];
    float s = 0.f;
#pragma unroll
    for (int i = 0; i < 3; i++) {
        int d = tid + i * 256;
        float x = ip[d];
        if (pos) x += pos[l * D_ + d] + tok[d];
        v[i] = x;
        s += x;
    }
#pragma unroll
    for (int o = 16; o > 0; o >>= 1) s += __shfl_xor_sync(0xffffffffu, s, o);

    __shared__ float red[8];
    __shared__ float smean, sinv;
    if (lane == 0) red[wid] = s;
    __syncthreads();
    if (tid == 0) {
        float t = 0.f;
#pragma unroll
        for (int j = 0; j < 8; j++) t += red[j];
        smean = t * (1.0f / 768.0f);
    }
    __syncthreads();
    float mean = smean;

    float ss = 0.f;
#pragma unroll
    for (int i = 0; i < 3; i++) {
        float d0 = v[i] - mean;
        ss += d0 * d0;
    }
#pragma unroll
    for (int o = 16; o > 0; o >>= 1) ss += __shfl_xor_sync(0xffffffffu, ss, o);
    if (lane == 0) red[wid] = ss;
    __syncthreads();
    if (tid == 0) {
        float t = 0.f;
#pragma unroll
        for (int j = 0; j < 8; j++) t += red[j];
        sinv = rsqrtf(t * (1.0f / 768.0f) + 1e-12f);
    }
    __syncthreads();
    float inv = sinv;

    float* op = out + (size_t)row * D_;
    uint32_t* ot = out_tf + (size_t)row * D_;
#pragma unroll
    for (int i = 0; i < 3; i++) {
        int d = tid + i * 256;
        float y = (v[i] - mean) * inv * g[d] + bta[d];
        op[d] = y;
        ot[d] = f2tf(y);
    }
}

// ============================================================================
// TF32 tensor-core attention (R4 structure; ctx stored as tf32 bits)
// ============================================================================
constexpr int KVW = 104;
constexpr int SW2 = 520;
constexpr int ATTN_SMEM = (64 * KVW * 2 + 64 * SW2) * 4 + L_ * 4;

__global__ __launch_bounds__(256)
void attn_mma(const float* __restrict__ qkv, float* __restrict__ ctx,
              const int* __restrict__ text_atts, const int* __restrict__ graph_mask)
{
    const int bh = blockIdx.x;
    const int b = bh / H_, h = bh % H_;
    const int qt = blockIdx.y;
    const int tid = threadIdx.x;
    const int lane = tid & 31, wid = tid >> 5;
    const int lq = lane >> 2, lr = lane & 3;

    extern __shared__ uint32_t smu[];
    uint32_t* Qs = smu;
    uint32_t* KV = Qs + 64 * KVW;
    uint32_t* Sb = KV + 64 * KVW;
    int* keep = (int*)(Sb + 64 * SW2);

    for (int j = tid; j < L_; j += 256)
        keep[j] = (j < NQ) ? 1
                : (j < TS) ? graph_mask[b * NN + (j - NQ)]
                           : text_atts[b * T_ + (j - TS)];

    const float* qbase = qkv + (size_t)(b * L_ + qt * 64) * QKVS + h * HD;
#pragma unroll
    for (int i = 0; i < 6; i++) {
        int e = tid + i * 256;
        int r = e / 24, c4 = (e % 24) * 4;
        float4 v = *(const float4*)(qbase + (size_t)r * QKVS + c4);
        uint32_t* p = &Qs[r * KVW + c4];
        p[0] = f2tf(v.x); p[1] = f2tf(v.y); p[2] = f2tf(v.z); p[3] = f2tf(v.w);
    }

    const int wm  = (wid >> 1) * 16;
    const int wnS = (wid & 1) * 32;
    const int wnV = (wid & 1) * 48;
    const float scale = 0.10206207261596577f;

    float4 pre[6];
    auto ldKV = [&](int kc, int which) {
        const float* base = qkv + (size_t)(b * L_ + kc * 64) * QKVS + which * D_ + h * HD;
#pragma unroll
        for (int i = 0; i < 6; i++) {
            int e = tid + i * 256;
            int r = e / 24, c4 = (e % 24) * 4;
            pre[i] = *(const float4*)(base + (size_t)r * QKVS + c4);
        }
    };
    auto stKV = [&]() {
#pragma unroll
        for (int i = 0; i < 6; i++) {
            int e = tid + i * 256;
            int r = e / 24, c4 = (e % 24) * 4;
            uint32_t* p = &KV[r * KVW + c4];
            p[0] = f2tf(pre[i].x); p[1] = f2tf(pre[i].y);
            p[2] = f2tf(pre[i].z); p[3] = f2tf(pre[i].w);
        }
    };

    // ---------------- score phase ----------------
    ldKV(0, 1);
    stKV();
    __syncthreads();
    for (int kc = 0; kc < 8; kc++) {
        if (kc < 7) ldKV(kc + 1, 1);

        float sacc[4][4];
#pragma unroll
        for (int nt = 0; nt < 4; nt++)
#pragma unroll
            for (int r = 0; r < 4; r++) sacc[nt][r] = 0.f;

#pragma unroll
        for (int k8 = 0; k8 < 96; k8 += 8) {
            uint32_t af[4];
            const uint32_t* qp = &Qs[(wm + lq) * KVW + k8 + lr];
            af[0] = qp[0];
            af[1] = qp[8 * KVW];
            af[2] = qp[4];
            af[3] = qp[8 * KVW + 4];
#pragma unroll
            for (int nt = 0; nt < 4; nt++) {
                const uint32_t* kp = &KV[(wnS + nt * 8 + lq) * KVW + k8 + lr];
                uint32_t bf[2] = {kp[0], kp[4]};
                mma_tf32(sacc[nt], af, bf);
            }
        }

        float* Sf = (float*)Sb;
#pragma unroll
        for (int nt = 0; nt < 4; nt++) {
            int kg = kc * 64 + wnS + nt * 8 + 2 * lr;
            bool k0 = keep[kg] != 0, k1 = keep[kg + 1] != 0;
#pragma unroll
            for (int half = 0; half < 2; half++) {
                int qrow = wm + lq + half * 8;
                int qg = qt * 64 + qrow;
                bool qok = keep[qg] != 0;
                bool ok0 = qok && k0, ok1 = qok && k1;
                if (qg < TS) {
                    if (kg     >= TS) ok0 = false;
                    if (kg + 1 >= TS) ok1 = false;
                } else {
                    if (kg     >= TS && qg < kg)     ok0 = false;
                    if (kg + 1 >= TS && qg < kg + 1) ok1 = false;
                }
                float v0 = sacc[nt][half * 2 + 0] * scale + (ok0 ? 0.f : NEGB);
                float v1 = sacc[nt][half * 2 + 1] * scale + (ok1 ? 0.f : NEGB);
                *(float2*)&Sf[qrow * SW2 + kg] = make_float2(v0, v1);
            }
        }
        __syncthreads();
        if (kc < 7) { stKV(); __syncthreads(); }
    }

    // ---------------- softmax: 4 threads per row ----------------
    ldKV(0, 2);
    {
        int r = tid >> 2, p = tid & 3;
        float* row = (float*)Sb + r * SW2 + p * 128;
        float m = -INFINITY;
#pragma unroll 4
        for (int k = 0; k < 128; k++) m = fmaxf(m, row[k]);
        m = fmaxf(m, __shfl_xor_sync(0xffffffffu, m, 1));
        m = fmaxf(m, __shfl_xor_sync(0xffffffffu, m, 2));
        float sum = 0.f;
#pragma unroll 4
        for (int k = 0; k < 128; k++) {
            float e = __expf(row[k] - m);
            row[k] = e;
            sum += e;
        }
        sum += __shfl_xor_sync(0xffffffffu, sum, 1);
        sum += __shfl_xor_sync(0xffffffffu, sum, 2);
        float inv = 1.f / sum;
        uint32_t* rowb = Sb + r * SW2 + p * 128;
#pragma unroll 4
        for (int k = 0; k < 128; k++) rowb[k] = f2tf(row[k] * inv);
    }
    stKV();
    __syncthreads();

    // ---------------- P @ V ----------------
    float oacc[6][4];
#pragma unroll
    for (int nt = 0; nt < 6; nt++)
#pragma unroll
        for (int r = 0; r < 4; r++) oacc[nt][r] = 0.f;

    for (int kc = 0; kc < 8; kc++) {
        if (kc < 7) ldKV(kc + 1, 2);

#pragma unroll
        for (int k8 = 0; k8 < 64; k8 += 8) {
            uint32_t af[4];
            const uint32_t* pp = &Sb[(wm + lq) * SW2 + kc * 64 + k8 + lr];
            af[0] = pp[0];
            af[1] = pp[8 * SW2];
            af[2] = pp[4];
            af[3] = pp[8 * SW2 + 4];
#pragma unroll
            for (int nt = 0; nt < 6; nt++) {
                const uint32_t* vp = &KV[(k8 + lr) * KVW + wnV + nt * 8 + lq];
                uint32_t bf[2] = {vp[0], vp[4 * KVW]};
                mma_tf32(oacc[nt], af, bf);
            }
        }
        __syncthreads();
        if (kc < 7) { stKV(); __syncthreads(); }
    }

#pragma unroll
    for (int nt = 0; nt < 6; nt++) {
#pragma unroll
        for (int half = 0; half < 2; half++) {
            int qrow = qt * 64 + wm + lq + half * 8;
            int col = h * HD + wnV + nt * 8 + 2 * lr;
            float2 o = make_float2(__uint_as_float(f2tf(oacc[nt][half * 2 + 0])),
                                   __uint_as_float(f2tf(oacc[nt][half * 2 + 1])));
            *(float2*)(ctx + (size_t)(b * L_ + qrow) * D_ + col) = o;
        }
    }
}

// ============================================================================
// misc elementwise
// ============================================================================
__global__ void fill_embed(const float* __restrict__ qtok,
                           const float* __restrict__ temb,
                           float* __restrict__ out)
{
    int idx = blockIdx.x * blockDim.x + threadIdx.x;
    if (idx >= B_ * L_ * D_) return;
    int rem = idx % (L_ * D_);
    int b = idx / (L_ * D_);
    int l = rem / D_, d = rem % D_;
    if (l < NQ)
        out[idx] = qtok[l * D_ + d];
    else if (l >= TS)
        out[idx] = temb[(size_t)(b * T_ + (l - TS)) * D_ + d];
}

__global__ void copy_out(const float* __restrict__ x, float* __restrict__ out, int n)
{
    int idx = blockIdx.x * blockDim.x + threadIdx.x;
    if (idx >= n) return;
    int rem = idx % (T_ * D_);
    int b = idx / (T_ * D_);
    int t = rem / D_, d = rem % D_;
    out[idx] = x[(size_t)(b * L_ + TS + t) * D_ + d];
}

// ============================================================================
// launcher
// ============================================================================
extern "C" void kernel_launch(void* const* d_in, const int* in_sizes, int n_in,
                              void* d_out, int out_size)
{
    const float* gnf     = (const float*)d_in[0];
    const float* temb    = (const float*)d_in[1];
    const int*   tatt    = (const int*)  d_in[2];
    const int*   gmask   = (const int*)  d_in[3];
    const float* qtok    = (const float*)d_in[4];
    const float* gproj_w = (const float*)d_in[5];
    const float* gproj_b = (const float*)d_in[6];
    const float* pos     = (const float*)d_in[7];
    const float* tok     = (const float*)d_in[8];
    const float* elng    = (const float*)d_in[9];
    const float* elnb    = (const float*)d_in[10];
    const float* qkvw    = (const float*)d_in[11];
    const float* qkvb    = (const float*)d_in[12];
    const float* aow     = (const float*)d_in[13];
    const float* aob     = (const float*)d_in[14];
    const float* ln1g    = (const float*)d_in[15];
    const float* ln1b    = (const float*)d_in[16];
    const float* ff1w    = (const float*)d_in[17];
    const float* ff1b    = (const float*)d_in[18];
    const float* ff2w    = (const float*)d_in[19];
    const float* ff2b    = (const float*)d_in[20];
    const float* ln2g    = (const float*)d_in[21];
    const float* ln2b    = (const float*)d_in[22];

    float *px, *ptmp, *pctx, *pqkv, *pff;
    uint32_t *pxtf, *pqkvwt, *paowt, *pff1wt, *pff2wt, *pgpwt, *pgnft;
    cudaGetSymbolAddress((void**)&px,    g_x);
    cudaGetSymbolAddress((void**)&ptmp,  g_tmp);
    cudaGetSymbolAddress((void**)&pctx,  g_ctx);
    cudaGetSymbolAddress((void**)&pqkv,  g_qkv);
    cudaGetSymbolAddress((void**)&pff,   g_ff);
    cudaGetSymbolAddress((void**)&pxtf,  g_xtf);
    cudaGetSymbolAddress((void**)&pqkvwt, g_qkvw_tf);
    cudaGetSymbolAddress((void**)&paowt,  g_aow_tf);
    cudaGetSymbolAddress((void**)&pff1wt, g_ff1w_tf);
    cudaGetSymbolAddress((void**)&pff2wt, g_ff2w_tf);
    cudaGetSymbolAddress((void**)&pgpwt,  g_gpw_tf);
    cudaGetSymbolAddress((void**)&pgnft,  g_gnf_tf);

    cudaFuncSetAttribute(attn_mma, cudaFuncAttributeMaxDynamicSharedMemorySize,
                         ATTN_SMEM);

    const int NROWS = B_ * L_;   // 8192

    // ---- pre-convert weights + graph features to tf32 (RNA) ----
    auto cvt = [](const float* in, uint32_t* out, int n) {
        cvt_tf<<<(n / 4 + 255) / 256, 256>>>(in, out, n);
    };
    cvt(qkvw,    pqkvwt, NLAY * D_ * 3 * D_);
    cvt(aow,     paowt,  NLAY * D_ * D_);
    cvt(ff1w,    pff1wt, NLAY * D_ * FF);
    cvt(ff2w,    pff2wt, NLAY * FF * D_);
    cvt(gproj_w, pgpwt,  D_ * D_);
    cvt(gnf,     pgnft,  B_ * NN * D_);

    // ---- embeddings ----
    fill_embed<<<(B_ * L_ * D_ + 255) / 256, 256>>>(qtok, temb, ptmp);
    tgemm<0><<<dim3(D_ / 128, (B_ * NN) / 128), 256>>>(
        pgnft, pgpwt, gproj_b, nullptr, ptmp, B_ * NN, D_, D_, 1);
    ln_kernel<<<NROWS, 256>>>(ptmp, px, pxtf, elng, elnb, pos, tok);

    // ---- 6 encoder layers ----
    for (int i = 0; i < NLAY; i++) {
        tgemm<0><<<dim3((3 * D_) / 128, NROWS / 128), 256>>>(
            pxtf, pqkvwt + (size_t)i * D_ * 3 * D_,
            qkvb + (size_t)i * 3 * D_, nullptr, pqkv, NROWS, 3 * D_, D_, 0);

        attn_mma<<<dim3(B_ * H_, L_ / 64), 256, ATTN_SMEM>>>(pqkv, pctx, tatt, gmask);

        tgemm<1><<<dim3(D_ / 128, NROWS / 128), 256>>>(
            (const uint32_t*)pctx, paowt + (size_t)i * D_ * D_,
            aob + (size_t)i * D_, px, ptmp, NROWS, D_, D_, 0);
        ln_kernel<<<NROWS, 256>>>(ptmp, px, pxtf, ln1g + (size_t)i * D_,
                                  ln1b + (size_t)i * D_, nullptr, nullptr);

        tgemm<2><<<dim3(FF / 128, NROWS / 128), 256>>>(
            pxtf, pff1wt + (size_t)i * D_ * FF,
            ff1b + (size_t)i * FF, nullptr, pff, NROWS, FF, D_, 0);

        tgemm<1><<<dim3(D_ / 128, NROWS / 128), 256>>>(
            (const uint32_t*)pff, pff2wt + (size_t)i * FF * D_,
            ff2b + (size_t)i * D_, px, ptmp, NROWS, D_, FF, 0);
        ln_kernel<<<NROWS, 256>>>(ptmp, px, pxtf, ln2g + (size_t)i * D_,
                                  ln2b + (size_t)i * D_, nullptr, nullptr);
    }

    // ---- output: text rows ----
    copy_out<<<(out_size + 255) / 256, 256>>>(px, (float*)d_out, out_size);
}

// round 8
// speedup vs baseline: 1.3748x; 1.0073x over previous
#include <cuda_runtime.h>
#include <math.h>
#include <stdint.h>

// ---------------- problem dims ----------------
constexpr int B_   = 16;
constexpr int NQ   = 32;
constexpr int NN   = 128;
constexpr int T_   = 352;
constexpr int D_   = 768;
constexpr int H_   = 8;
constexpr int NLAY = 6;
constexpr int FF   = 3072;
constexpr int L_   = NQ + NN + T_;   // 512
constexpr int TS   = NQ + NN;        // 160
constexpr int HD   = D_ / H_;        // 96
constexpr float NEGB = -1e9f;
constexpr int QKVS = 3 * D_;         // 2304

// ---------------- device scratch ----------------
__device__ float g_x  [B_ * L_ * D_];
__device__ float g_tmp[B_ * L_ * D_];
__device__ float g_ctx[B_ * L_ * D_];      // tf32-bit floats (attention out)
__device__ float g_qkv[B_ * L_ * 3 * D_];  // tf32-bit floats (EPI=3 epilogue)
__device__ float g_ff [B_ * L_ * FF];      // tf32-bit floats (gelu out)

// tf32 pre-converted operand copies
__device__ uint32_t g_xtf    [B_ * L_ * D_];
__device__ uint32_t g_qkvw_tf[NLAY * D_ * 3 * D_];
__device__ uint32_t g_aow_tf [NLAY * D_ * D_];
__device__ uint32_t g_ff1w_tf[NLAY * D_ * FF];
__device__ uint32_t g_ff2w_tf[NLAY * FF * D_];
__device__ uint32_t g_gpw_tf [D_ * D_];
__device__ uint32_t g_gnf_tf [B_ * NN * D_];

// ---------------- tf32 helpers ----------------
__device__ __forceinline__ uint32_t f2tf(float x) {
    uint32_t r;
    asm("cvt.rna.tf32.f32 %0, %1;" : "=r"(r) : "f"(x));
    return r;
}

__device__ __forceinline__ void mma_tf32(float c[4], const uint32_t a[4],
                                         const uint32_t b[2]) {
    asm volatile(
        "mma.sync.aligned.m16n8k8.row.col.f32.tf32.tf32.f32 "
        "{%0,%1,%2,%3}, {%4,%5,%6,%7}, {%8,%9}, {%0,%1,%2,%3};"
        : "+f"(c[0]), "+f"(c[1]), "+f"(c[2]), "+f"(c[3])
        : "r"(a[0]), "r"(a[1]), "r"(a[2]), "r"(a[3]), "r"(b[0]), "r"(b[1]));
}

// ============================================================================
// TF32 GEMM — register-staged double-buffered mainloop (measured-good).
// EPI: 0 = +bias fp32   1 = +bias+resid fp32   2 = gelu tf32   3 = +bias tf32
// ============================================================================
constexpr int ASTR = 20;
constexpr int BSTR = 136;

template <int EPI>
__global__ __launch_bounds__(256)
void tgemm(const uint32_t* __restrict__ A, const uint32_t* __restrict__ Bm,
           const float* __restrict__ bias, const float* __restrict__ resid,
           float* __restrict__ C, int M, int N, int K, int mapGraph)
{
    __shared__ uint32_t As[2][128 * ASTR];
    __shared__ uint32_t Bs[2][16 * BSTR];

    const int tid  = threadIdx.x;
    const int br   = blockIdx.y, bc = blockIdx.x;
    const int lane = tid & 31,  wid = tid >> 5;
    const int wm = (wid >> 2) * 64;
    const int wn = (wid & 3) * 32;
    const int lq = lane >> 2;
    const int lr = lane & 3;

    float acc[4][4][4];
#pragma unroll
    for (int mt = 0; mt < 4; mt++)
#pragma unroll
        for (int nt = 0; nt < 4; nt++)
#pragma unroll
            for (int r = 0; r < 4; r++) acc[mt][nt][r] = 0.f;

    const int nkt = K >> 4;
    uint4 pa[2], pb[2];

    auto ldA = [&](int kt) {
#pragma unroll
        for (int i = 0; i < 2; i++) {
            int id  = tid + i * 256;
            int row = id >> 2, cg = (id & 3) << 2;
            pa[i] = *(const uint4*)(A + (size_t)(br * 128 + row) * K + kt * 16 + cg);
        }
    };
    auto ldB = [&](int kt) {
#pragma unroll
        for (int i = 0; i < 2; i++) {
            int id  = tid + i * 256;
            int row = id >> 5, cg = (id & 31) << 2;
            pb[i] = *(const uint4*)(Bm + (size_t)(kt * 16 + row) * N + bc * 128 + cg);
        }
    };
    auto stAB = [&](int buf) {
#pragma unroll
        for (int i = 0; i < 2; i++) {
            int id  = tid + i * 256;
            int row = id >> 2, cg = (id & 3) << 2;
            *(uint4*)&As[buf][row * ASTR + cg] = pa[i];
        }
#pragma unroll
        for (int i = 0; i < 2; i++) {
            int id  = tid + i * 256;
            int row = id >> 5, cg = (id & 31) << 2;
            *(uint4*)&Bs[buf][row * BSTR + cg] = pb[i];
        }
    };
    auto compute = [&](int buf) {
#pragma unroll
        for (int k8 = 0; k8 < 16; k8 += 8) {
            uint32_t af[4][4], bf[4][2];
#pragma unroll
            for (int mt = 0; mt < 4; mt++) {
                const uint32_t* p = &As[buf][(wm + mt * 16 + lq) * ASTR + k8 + lr];
                af[mt][0] = p[0];
                af[mt][1] = p[8 * ASTR];
                af[mt][2] = p[4];
                af[mt][3] = p[8 * ASTR + 4];
            }
#pragma unroll
            for (int nt = 0; nt < 4; nt++) {
                const uint32_t* p = &Bs[buf][(k8 + lr) * BSTR + wn + nt * 8 + lq];
                bf[nt][0] = p[0];
                bf[nt][1] = p[4 * BSTR];
            }
#pragma unroll
            for (int mt = 0; mt < 4; mt++)
#pragma unroll
                for (int nt = 0; nt < 4; nt++)
                    mma_tf32(acc[mt][nt], af[mt], bf[nt]);
        }
    };

    ldA(0); ldB(0);
    stAB(0);
    __syncthreads();
    for (int kt = 0; kt < nkt; kt++) {
        int buf = kt & 1;
        bool more = (kt + 1 < nkt);
        if (more) { ldA(kt + 1); ldB(kt + 1); }
        compute(buf);
        if (more) stAB(buf ^ 1);
        __syncthreads();
    }

    // ---- epilogue ----
#pragma unroll
    for (int mt = 0; mt < 4; mt++) {
        int rbase = br * 128 + wm + mt * 16 + lq;
#pragma unroll
        for (int nt = 0; nt < 4; nt++) {
            int col = bc * 128 + wn + nt * 8 + lr * 2;
            float b0 = bias[col], b1 = bias[col + 1];
#pragma unroll
            for (int hh = 0; hh < 2; hh++) {
                int row = rbase + hh * 8;
                int orow = mapGraph ? (row / NN) * L_ + NQ + (row % NN) : row;
                float v0 = acc[mt][nt][hh * 2 + 0] + b0;
                float v1 = acc[mt][nt][hh * 2 + 1] + b1;
                if (EPI == 1) {
                    v0 += resid[(size_t)row * N + col];
                    v1 += resid[(size_t)row * N + col + 1];
                }
                if (EPI == 2) {
                    v0 = 0.5f * v0 * (1.0f + erff(v0 * 0.7071067811865475f));
                    v1 = 0.5f * v1 * (1.0f + erff(v1 * 0.7071067811865475f));
                }
                if (EPI == 2 || EPI == 3) {   // consumed as tf32 downstream
                    v0 = __uint_as_float(f2tf(v0));
                    v1 = __uint_as_float(f2tf(v1));
                }
                float2 o = make_float2(v0, v1);
                *(float2*)(C + (size_t)orow * N + col) = o;
            }
        }
    }
}

// ============================================================================
// tf32 conversion pass (weights / inputs); n multiple of 4
// ============================================================================
__global__ void cvt_tf(const float* __restrict__ in, uint32_t* __restrict__ out,
                       int n)
{
    int i = (blockIdx.x * blockDim.x + threadIdx.x) * 4;
    if (i >= n) return;
    float4 v = *(const float4*)(in + i);
    uint4 o = make_uint4(f2tf(v.x), f2tf(v.y), f2tf(v.z), f2tf(v.w));
    *(uint4*)(out + i) = o;
}

// ============================================================================
// Row LayerNorm (D=768), warp-shuffle reductions; dual fp32 + tf32 output
// ============================================================================
__global__ __launch_bounds__(256)
void ln_kernel(const float* __restrict__ in, float* __restrict__ out,
               uint32_t* __restrict__ out_tf,
               const float* __restrict__ g, const float* __restrict__ bta,
               const float* __restrict__ pos, const float* __restrict__ tok)
{
    const int row = blockIdx.x;
    const int l = row % L_;
    const int tid = threadIdx.x;
    const int lane = tid & 31, wid = tid >> 5;
    const float* ip = in + (size_t)row * D_;

    float v[3];
    float s = 0.f;
#pragma unroll
    for (int i = 0; i < 3; i++) {
        int d = tid + i * 256;
        float x = ip[d];
        if (pos) x += pos[l * D_ + d] + tok[d];
        v[i] = x;
        s += x;
    }
#pragma unroll
    for (int o = 16; o > 0; o >>= 1) s += __shfl_xor_sync(0xffffffffu, s, o);

    __shared__ float red[8];
    __shared__ float smean, sinv;
    if (lane == 0) red[wid] = s;
    __syncthreads();
    if (tid == 0) {
        float t = 0.f;
#pragma unroll
        for (int j = 0; j < 8; j++) t += red[j];
        smean = t * (1.0f / 768.0f);
    }
    __syncthreads();
    float mean = smean;

    float ss = 0.f;
#pragma unroll
    for (int i = 0; i < 3; i++) {
        float d0 = v[i] - mean;
        ss += d0 * d0;
    }
#pragma unroll
    for (int o = 16; o > 0; o >>= 1) ss += __shfl_xor_sync(0xffffffffu, ss, o);
    if (lane == 0) red[wid] = ss;
    __syncthreads();
    if (tid == 0) {
        float t = 0.f;
#pragma unroll
        for (int j = 0; j < 8; j++) t += red[j];
        sinv = rsqrtf(t * (1.0f / 768.0f) + 1e-12f);
    }
    __syncthreads();
    float inv = sinv;

    float* op = out + (size_t)row * D_;
    uint32_t* ot = out_tf + (size_t)row * D_;
#pragma unroll
    for (int i = 0; i < 3; i++) {
        int d = tid + i * 256;
        float y = (v[i] - mean) * inv * g[d] + bta[d];
        op[d] = y;
        ot[d] = f2tf(y);
    }
}

// ============================================================================
// TF32 tensor-core attention, double-buffered KV, qkv already tf32 bits.
// One __syncthreads per KV chunk (was two). Pure uint4 smem fills.
// ============================================================================
constexpr int KVW = 104;
constexpr int SW2 = 520;
// Q[64][KVW] + KV double buffer 2*[64][KVW] + S[64][SW2] + keep[512]
constexpr int ATTN_SMEM = (64 * KVW * 3 + 64 * SW2) * 4 + L_ * 4;  // 215040 B

__global__ __launch_bounds__(256)
void attn_mma(const uint32_t* __restrict__ qkv, float* __restrict__ ctx,
              const int* __restrict__ text_atts, const int* __restrict__ graph_mask)
{
    const int bh = blockIdx.x;
    const int b = bh / H_, h = bh % H_;
    const int qt = blockIdx.y;
    const int tid = threadIdx.x;
    const int lane = tid & 31, wid = tid >> 5;
    const int lq = lane >> 2, lr = lane & 3;

    extern __shared__ uint32_t smu[];
    uint32_t* Qs  = smu;                       // [64][KVW]
    uint32_t* KVb = Qs + 64 * KVW;             // 2 x [64][KVW]
    uint32_t* Sb  = KVb + 2 * 64 * KVW;        // [64][SW2]
    int* keep = (int*)(Sb + 64 * SW2);         // [512]

    for (int j = tid; j < L_; j += 256)
        keep[j] = (j < NQ) ? 1
                : (j < TS) ? graph_mask[b * NN + (j - NQ)]
                           : text_atts[b * T_ + (j - TS)];

    // Q tile -> smem (already tf32 bits; plain vector copy)
    const uint32_t* qbase = qkv + (size_t)(b * L_ + qt * 64) * QKVS + h * HD;
#pragma unroll
    for (int i = 0; i < 6; i++) {
        int e = tid + i * 256;
        int r = e / 24, c4 = (e % 24) * 4;
        *(uint4*)&Qs[r * KVW + c4] = *(const uint4*)(qbase + (size_t)r * QKVS + c4);
    }

    const int wm  = (wid >> 1) * 16;
    const int wnS = (wid & 1) * 32;
    const int wnV = (wid & 1) * 48;
    const float scale = 0.10206207261596577f;   // 1/sqrt(96)

    uint4 pre[6];
    auto ldKV = [&](int kc, int which) {   // which: 1=K, 2=V
        const uint32_t* base = qkv + (size_t)(b * L_ + kc * 64) * QKVS + which * D_ + h * HD;
#pragma unroll
        for (int i = 0; i < 6; i++) {
            int e = tid + i * 256;
            int r = e / 24, c4 = (e % 24) * 4;
            pre[i] = *(const uint4*)(base + (size_t)r * QKVS + c4);
        }
    };
    auto stKV = [&](int buf) {
        uint32_t* KV = KVb + buf * 64 * KVW;
#pragma unroll
        for (int i = 0; i < 6; i++) {
            int e = tid + i * 256;
            int r = e / 24, c4 = (e % 24) * 4;
            *(uint4*)&KV[r * KVW + c4] = pre[i];
        }
    };

    // ---------------- score phase ----------------
    ldKV(0, 1);
    stKV(0);
    __syncthreads();             // publishes Q, keep, K chunk 0
    for (int kc = 0; kc < 8; kc++) {
        if (kc < 7) ldKV(kc + 1, 1);

        const uint32_t* KV = KVb + (kc & 1) * 64 * KVW;
        float sacc[4][4];
#pragma unroll
        for (int nt = 0; nt < 4; nt++)
#pragma unroll
            for (int r = 0; r < 4; r++) sacc[nt][r] = 0.f;

#pragma unroll
        for (int k8 = 0; k8 < 96; k8 += 8) {
            uint32_t af[4];
            const uint32_t* qp = &Qs[(wm + lq) * KVW + k8 + lr];
            af[0] = qp[0];
            af[1] = qp[8 * KVW];
            af[2] = qp[4];
            af[3] = qp[8 * KVW + 4];
#pragma unroll
            for (int nt = 0; nt < 4; nt++) {
                const uint32_t* kp = &KV[(wnS + nt * 8 + lq) * KVW + k8 + lr];
                uint32_t bf[2] = {kp[0], kp[4]};
                mma_tf32(sacc[nt], af, bf);
            }
        }

        if (kc < 7) stKV((kc + 1) & 1);   // other buffer; prev readers fenced by last sync

        float* Sf = (float*)Sb;
#pragma unroll
        for (int nt = 0; nt < 4; nt++) {
            int kg = kc * 64 + wnS + nt * 8 + 2 * lr;
            bool k0 = keep[kg] != 0, k1 = keep[kg + 1] != 0;
#pragma unroll
            for (int half = 0; half < 2; half++) {
                int qrow = wm + lq + half * 8;
                int qg = qt * 64 + qrow;
                bool qok = keep[qg] != 0;
                bool ok0 = qok && k0, ok1 = qok && k1;
                if (qg < TS) {                       // prefix cannot see text
                    if (kg     >= TS) ok0 = false;
                    if (kg + 1 >= TS) ok1 = false;
                } else {                             // text query: causal in text
                    if (kg     >= TS && qg < kg)     ok0 = false;
                    if (kg + 1 >= TS && qg < kg + 1) ok1 = false;
                }
                float v0 = sacc[nt][half * 2 + 0] * scale + (ok0 ? 0.f : NEGB);
                float v1 = sacc[nt][half * 2 + 1] * scale + (ok1 ? 0.f : NEGB);
                *(float2*)&Sf[qrow * SW2 + kg] = make_float2(v0, v1);
            }
        }
        __syncthreads();         // one barrier per chunk
    }

    // ---------------- softmax: 4 threads per row (thread-local, no block sync) --
    ldKV(0, 2);                  // prefetch V chunk 0 under softmax
    {
        int r = tid >> 2, p = tid & 3;
        float* row = (float*)Sb + r * SW2 + p * 128;
        float m = -INFINITY;
#pragma unroll 4
        for (int k = 0; k < 128; k++) m = fmaxf(m, row[k]);
        m = fmaxf(m, __shfl_xor_sync(0xffffffffu, m, 1));
        m = fmaxf(m, __shfl_xor_sync(0xffffffffu, m, 2));
        float sum = 0.f;
#pragma unroll 4
        for (int k = 0; k < 128; k++) {
            float e = __expf(row[k] - m);
            row[k] = e;
            sum += e;
        }
        sum += __shfl_xor_sync(0xffffffffu, sum, 1);
        sum += __shfl_xor_sync(0xffffffffu, sum, 2);
        float inv = 1.f / sum;
        uint32_t* rowb = Sb + r * SW2 + p * 128;
#pragma unroll 4
        for (int k = 0; k < 128; k++) rowb[k] = f2tf(row[k] * inv);
    }
    stKV(0);
    __syncthreads();             // S fully written + V chunk 0 ready

    // ---------------- P @ V phase ----------------
    float oacc[6][4];
#pragma unroll
    for (int nt = 0; nt < 6; nt++)
#pragma unroll
        for (int r = 0; r < 4; r++) oacc[nt][r] = 0.f;

    for (int kc = 0; kc < 8; kc++) {
        if (kc < 7) ldKV(kc + 1, 2);

        const uint32_t* KV = KVb + (kc & 1) * 64 * KVW;
#pragma unroll
        for (int k8 = 0; k8 < 64; k8 += 8) {
            uint32_t af[4];
            const uint32_t* pp = &Sb[(wm + lq) * SW2 + kc * 64 + k8 + lr];
            af[0] = pp[0];
            af[1] = pp[8 * SW2];
            af[2] = pp[4];
            af[3] = pp[8 * SW2 + 4];
#pragma unroll
            for (int nt = 0; nt < 6; nt++) {
                const uint32_t* vp = &KV[(k8 + lr) * KVW + wnV + nt * 8 + lq];
                uint32_t bf[2] = {vp[0], vp[4 * KVW]};
                mma_tf32(oacc[nt], af, bf);
            }
        }

        if (kc < 7) {
            stKV((kc + 1) & 1);
            __syncthreads();
        }
    }

#pragma unroll
    for (int nt = 0; nt < 6; nt++) {
#pragma unroll
        for (int half = 0; half < 2; half++) {
            int qrow = qt * 64 + wm + lq + half * 8;
            int col = h * HD + wnV + nt * 8 + 2 * lr;
            // store as tf32 bits: consumed directly as GEMM-A by attn-out GEMM
            float2 o = make_float2(__uint_as_float(f2tf(oacc[nt][half * 2 + 0])),
                                   __uint_as_float(f2tf(oacc[nt][half * 2 + 1])));
            *(float2*)(ctx + (size_t)(b * L_ + qrow) * D_ + col) = o;
        }
    }
}

// ============================================================================
// misc elementwise
// ============================================================================
__global__ void fill_embed(const float* __restrict__ qtok,
                           const float* __restrict__ temb,
                           float* __restrict__ out)
{
    int idx = blockIdx.x * blockDim.x + threadIdx.x;
    if (idx >= B_ * L_ * D_) return;
    int rem = idx % (L_ * D_);
    int b = idx / (L_ * D_);
    int l = rem / D_, d = rem % D_;
    if (l < NQ)
        out[idx] = qtok[l * D_ + d];
    else if (l >= TS)
        out[idx] = temb[(size_t)(b * T_ + (l - TS)) * D_ + d];
}

__global__ void copy_out(const float* __restrict__ x, float* __restrict__ out, int n)
{
    int idx = blockIdx.x * blockDim.x + threadIdx.x;
    if (idx >= n) return;
    int rem = idx % (T_ * D_);
    int b = idx / (T_ * D_);
    int t = rem / D_, d = rem % D_;
    out[idx] = x[(size_t)(b * L_ + TS + t) * D_ + d];
}

// ============================================================================
// launcher
// ============================================================================
extern "C" void kernel_launch(void* const* d_in, const int* in_sizes, int n_in,
                              void* d_out, int out_size)
{
    const float* gnf     = (const float*)d_in[0];
    const float* temb    = (const float*)d_in[1];
    const int*   tatt    = (const int*)  d_in[2];
    const int*   gmask   = (const int*)  d_in[3];
    const float* qtok    = (const float*)d_in[4];
    const float* gproj_w = (const float*)d_in[5];
    const float* gproj_b = (const float*)d_in[6];
    const float* pos     = (const float*)d_in[7];
    const float* tok     = (const float*)d_in[8];
    const float* elng    = (const float*)d_in[9];
    const float* elnb    = (const float*)d_in[10];
    const float* qkvw    = (const float*)d_in[11];
    const float* qkvb    = (const float*)d_in[12];
    const float* aow     = (const float*)d_in[13];
    const float* aob     = (const float*)d_in[14];
    const float* ln1g    = (const float*)d_in[15];
    const float* ln1b    = (const float*)d_in[16];
    const float* ff1w    = (const float*)d_in[17];
    const float* ff1b    = (const float*)d_in[18];
    const float* ff2w    = (const float*)d_in[19];
    const float* ff2b    = (const float*)d_in[20];
    const float* ln2g    = (const float*)d_in[21];
    const float* ln2b    = (const float*)d_in[22];

    float *px, *ptmp, *pctx, *pqkv, *pff;
    uint32_t *pxtf, *pqkvwt, *paowt, *pff1wt, *pff2wt, *pgpwt, *pgnft;
    cudaGetSymbolAddress((void**)&px,    g_x);
    cudaGetSymbolAddress((void**)&ptmp,  g_tmp);
    cudaGetSymbolAddress((void**)&pctx,  g_ctx);
    cudaGetSymbolAddress((void**)&pqkv,  g_qkv);
    cudaGetSymbolAddress((void**)&pff,   g_ff);
    cudaGetSymbolAddress((void**)&pxtf,  g_xtf);
    cudaGetSymbolAddress((void**)&pqkvwt, g_qkvw_tf);
    cudaGetSymbolAddress((void**)&paowt,  g_aow_tf);
    cudaGetSymbolAddress((void**)&pff1wt, g_ff1w_tf);
    cudaGetSymbolAddress((void**)&pff2wt, g_ff2w_tf);
    cudaGetSymbolAddress((void**)&pgpwt,  g_gpw_tf);
    cudaGetSymbolAddress((void**)&pgnft,  g_gnf_tf);

    cudaFuncSetAttribute(attn_mma, cudaFuncAttributeMaxDynamicSharedMemorySize,
                         ATTN_SMEM);

    const int NROWS = B_ * L_;   // 8192

    // ---- pre-convert weights + graph features to tf32 (RNA) ----
    auto cvt = [](const float* in, uint32_t* out, int n) {
        cvt_tf<<<(n / 4 + 255) / 256, 256>>>(in, out, n);
    };
    cvt(qkvw,    pqkvwt, NLAY * D_ * 3 * D_);
    cvt(aow,     paowt,  NLAY * D_ * D_);
    cvt(ff1w,    pff1wt, NLAY * D_ * FF);
    cvt(ff2w,    pff2wt, NLAY * FF * D_);
    cvt(gproj_w, pgpwt,  D_ * D_);
    cvt(gnf,     pgnft,  B_ * NN * D_);

    // ---- embeddings ----
    fill_embed<<<(B_ * L_ * D_ + 255) / 256, 256>>>(qtok, temb, ptmp);
    tgemm<0><<<dim3(D_ / 128, (B_ * NN) / 128), 256>>>(
        pgnft, pgpwt, gproj_b, nullptr, ptmp, B_ * NN, D_, D_, 1);
    ln_kernel<<<NROWS, 256>>>(ptmp, px, pxtf, elng, elnb, pos, tok);

    // ---- 6 encoder layers ----
    for (int i = 0; i < NLAY; i++) {
        // qkv projection — EPI=3 writes tf32 bits for the attention kernel
        tgemm<3><<<dim3((3 * D_) / 128, NROWS / 128), 256>>>(
            pxtf, pqkvwt + (size_t)i * D_ * 3 * D_,
            qkvb + (size_t)i * 3 * D_, nullptr, pqkv, NROWS, 3 * D_, D_, 0);

        attn_mma<<<dim3(B_ * H_, L_ / 64), 256, ATTN_SMEM>>>(
            (const uint32_t*)pqkv, pctx, tatt, gmask);

        tgemm<1><<<dim3(D_ / 128, NROWS / 128), 256>>>(
            (const uint32_t*)pctx, paowt + (size_t)i * D_ * D_,
            aob + (size_t)i * D_, px, ptmp, NROWS, D_, D_, 0);
        ln_kernel<<<NROWS, 256>>>(ptmp, px, pxtf, ln1g + (size_t)i * D_,
                                  ln1b + (size_t)i * D_, nullptr, nullptr);

        tgemm<2><<<dim3(FF / 128, NROWS / 128), 256>>>(
            pxtf, pff1wt + (size_t)i * D_ * FF,
            ff1b + (size_t)i * FF, nullptr, pff, NROWS, FF, D_, 0);

        tgemm<1><<<dim3(D_ / 128, NROWS / 128), 256>>>(
            (const uint32_t*)pff, pff2wt + (size_t)i * FF * D_,
            ff2b + (size_t)i * D_, px, ptmp, NROWS, D_, FF, 0);
        ln_kernel<<<NROWS, 256>>>(ptmp, px, pxtf, ln2g + (size_t)i * D_,
                                  ln2b + (size_t)i * D_, nullptr, nullptr);
    }

    // ---- output: text rows ----
    copy_out<<<(out_size + 255) / 256, 256>>>(px, (float*)d_out, out_size);
}